// round 1
// baseline (speedup 1.0000x reference)
#include <cuda_runtime.h>

// GCN_75050258530542
// out[n,64] = norm_d[n] * (sum_{e: dst[e]==n} x[src[e],15:25]*norm_s[src[e]]) @ (W1@W2)
//             + (b1@W2 + b2)
// MLP collapsed into a single 10x64 effective weight since there is no nonlinearity.

constexpr int NMAX = 100000;
constexpr int FP   = 12;   // 10 features padded to 12 floats (48B, 16B-aligned rows)

__device__ __align__(16) float g_deg[2 * NMAX];     // [0..N): deg_out, [NMAX..): deg_in
__device__ __align__(16) float g_xsn[NMAX * FP];    // x[:,15:25] * norm_s, padded
__device__ __align__(16) float g_agg[NMAX * FP];    // scatter target
__device__ float g_normd[NMAX];
__device__ float g_Weff[640];                       // W1@W2  (10 x 64)
__device__ float g_beff[64];                        // b1@W2 + b2

// ---------------------------------------------------------------- zero scratch
__global__ void k_zero(int n_agg) {
    int i = blockIdx.x * blockDim.x + threadIdx.x;
    int stride = gridDim.x * blockDim.x;
    for (int k = i; k < 2 * NMAX; k += stride) g_deg[k] = 0.f;
    for (int k = i; k < n_agg; k += stride) g_agg[k] = 0.f;
}

// ---------------------------------------------------------------- degrees
__global__ void k_degree(const int* __restrict__ src, const int* __restrict__ dst, int E) {
    int t = blockIdx.x * blockDim.x + threadIdx.x;
    int nq = E >> 2;
    if (t < nq) {
        int4 s = reinterpret_cast<const int4*>(src)[t];
        int4 d = reinterpret_cast<const int4*>(dst)[t];
        atomicAdd(&g_deg[s.x], 1.f);
        atomicAdd(&g_deg[s.y], 1.f);
        atomicAdd(&g_deg[s.z], 1.f);
        atomicAdd(&g_deg[s.w], 1.f);
        atomicAdd(&g_deg[NMAX + d.x], 1.f);
        atomicAdd(&g_deg[NMAX + d.y], 1.f);
        atomicAdd(&g_deg[NMAX + d.z], 1.f);
        atomicAdd(&g_deg[NMAX + d.w], 1.f);
    }
    if (t == 0) {
        for (int e = (nq << 2); e < E; e++) {
            atomicAdd(&g_deg[src[e]], 1.f);
            atomicAdd(&g_deg[NMAX + dst[e]], 1.f);
        }
    }
}

// ---------------------------------------------------------------- per-node prep
__global__ void k_prep(const float* __restrict__ x, int N) {
    int i = blockIdx.x * blockDim.x + threadIdx.x;
    if (i >= N) return;
    float dout = g_deg[i];
    float din  = g_deg[NMAX + i];
    float ns = 1.0f / sqrtf(dout > 0.f ? dout : 1.f);
    float nd = 1.0f / sqrtf(din  > 0.f ? din  : 1.f);
    g_normd[i] = nd;
    const float* xr = x + (size_t)i * 40 + 15;
    float* o = g_xsn + i * FP;
#pragma unroll
    for (int k = 0; k < 10; k++) o[k] = xr[k] * ns;
}

// ---------------------------------------------------------------- vector REDs
__device__ __forceinline__ void red4(float* p, float4 v) {
    asm volatile("red.global.add.v4.f32 [%0], {%1,%2,%3,%4};"
                 :: "l"(p), "f"(v.x), "f"(v.y), "f"(v.z), "f"(v.w) : "memory");
}
__device__ __forceinline__ void red2(float* p, float2 v) {
    asm volatile("red.global.add.v2.f32 [%0], {%1,%2};"
                 :: "l"(p), "f"(v.x), "f"(v.y) : "memory");
}

// ---------------------------------------------------------------- edge scatter
__global__ void k_scatter(const int* __restrict__ src, const int* __restrict__ dst, int E) {
    int t = blockIdx.x * blockDim.x + threadIdx.x;
    int nq = E >> 2;
    if (t < nq) {
        int4 s = reinterpret_cast<const int4*>(src)[t];
        int4 d = reinterpret_cast<const int4*>(dst)[t];
        int ss[4] = {s.x, s.y, s.z, s.w};
        int dd[4] = {d.x, d.y, d.z, d.w};
        float4 A[4], B[4];
        float2 C[4];
#pragma unroll
        for (int j = 0; j < 4; j++) {
            const float* r = g_xsn + ss[j] * FP;
            A[j] = *reinterpret_cast<const float4*>(r);
            B[j] = *reinterpret_cast<const float4*>(r + 4);
            C[j] = *reinterpret_cast<const float2*>(r + 8);
        }
#pragma unroll
        for (int j = 0; j < 4; j++) {
            float* a = g_agg + dd[j] * FP;
            red4(a,     A[j]);
            red4(a + 4, B[j]);
            red2(a + 8, C[j]);
        }
    }
    if (t == 0) {
        for (int e = (nq << 2); e < E; e++) {
            const float* r = g_xsn + src[e] * FP;
            float* a = g_agg + dst[e] * FP;
#pragma unroll
            for (int k = 0; k < 10; k++) atomicAdd(a + k, r[k]);
        }
    }
}

// ---------------------------------------------------------------- fold MLP: Weff = W1@W2, beff = b1@W2+b2
__global__ void k_weff(const float* __restrict__ W1, const float* __restrict__ b1,
                       const float* __restrict__ W2, const float* __restrict__ b2) {
    int t = threadIdx.x;
    if (t < 640) {
        int i = t >> 6, j = t & 63;
        float s = 0.f;
#pragma unroll 8
        for (int k = 0; k < 128; k++) s += W1[i * 128 + k] * W2[k * 64 + j];
        g_Weff[t] = s;
    } else if (t < 704) {
        int j = t - 640;
        float s = b2[j];
#pragma unroll 8
        for (int k = 0; k < 128; k++) s += b1[k] * W2[k * 64 + j];
        g_beff[j] = s;
    }
}

// ---------------------------------------------------------------- output: per node 10x64 matvec
__global__ void k_out(float* __restrict__ out, int N) {
    __shared__ float sW[640];
    __shared__ float sb[64];
    int t = threadIdx.x;
    for (int k = t; k < 640; k += 256) sW[k] = g_Weff[k];
    if (t < 64) sb[t] = g_beff[t];
    __syncthreads();
    int node = blockIdx.x * 4 + (t >> 6);
    if (node >= N) return;
    int j = t & 63;
    const float* ar = g_agg + node * FP;
    float nd = g_normd[node];
    float4 a0 = *reinterpret_cast<const float4*>(ar);
    float4 a1 = *reinterpret_cast<const float4*>(ar + 4);
    float2 a2 = *reinterpret_cast<const float2*>(ar + 8);
    float a[10] = {a0.x, a0.y, a0.z, a0.w, a1.x, a1.y, a1.z, a1.w, a2.x, a2.y};
    float acc = sb[j];
#pragma unroll
    for (int k = 0; k < 10; k++) acc += (a[k] * nd) * sW[k * 64 + j];
    out[(size_t)node * 64 + j] = acc;
}

// ---------------------------------------------------------------- launch
extern "C" void kernel_launch(void* const* d_in, const int* in_sizes, int n_in,
                              void* d_out, int out_size) {
    const float* x   = (const float*)d_in[0];
    const int*   src = (const int*)d_in[1];
    const int*   dst = (const int*)d_in[2];
    const float* W1  = (const float*)d_in[3];
    const float* b1  = (const float*)d_in[4];
    const float* W2  = (const float*)d_in[5];
    const float* b2  = (const float*)d_in[6];
    float* out = (float*)d_out;

    int N = in_sizes[0] / 40;
    int E = in_sizes[1];
    int nq = E >> 2;
    int eb = nq > 0 ? (nq + 255) / 256 : 1;

    k_zero<<<1024, 256>>>(N * FP);
    k_weff<<<1, 704>>>(W1, b1, W2, b2);
    k_degree<<<eb, 256>>>(src, dst, E);
    k_prep<<<(N + 255) / 256, 256>>>(x, N);
    k_scatter<<<eb, 256>>>(src, dst, E);
    k_out<<<(N + 3) / 4, 256>>>(out, N);
}